// round 5
// baseline (speedup 1.0000x reference)
#include <cuda_runtime.h>
#include <cuda_bf16.h>

// ---------------------------------------------------------------------------
// MultiscaleMessagePassing on GB300 (sm_103a)
//
// Outputs (concatenated float32 in d_out):
//   [0 .. 16,777,216)                 coarse_node_attrs  [65536, 256]
//   [16,777,216 .. 83,886,080)        coarse_edge_attrs  [262144, 256]
//   [83,886,080 .. 84,410,368)        coarse_edge_index  [2, 262144] (cast)
// ---------------------------------------------------------------------------

#define H         256
#define N_FINE    262144
#define E_FINE    524288
#define N_COARSE  65536
#define E_COARSE  262144

#define NODE_OUT_F   (N_COARSE * H)           // 16,777,216
#define EDGE_OUT_F   (E_COARSE * H)           // 67,108,864
#define ATTR_OUT_F   (NODE_OUT_F + EDGE_OUT_F) // 83,886,080
#define IDX_OUT_F    (2 * E_COARSE)           // 524,288

// scratch (device globals; no allocation)
__device__ __align__(16) __nv_bfloat16 g_WT_hi[3 * H * H];
__device__ __align__(16) __nv_bfloat16 g_WT_lo[3 * H * H];
__device__ int g_ncnt[N_COARSE];
__device__ int g_ecnt[E_COARSE];

// ------------------------- small helpers -----------------------------------

__device__ __forceinline__ void mma16816(float c[4], const unsigned a[4],
                                         unsigned b0, unsigned b1) {
    asm volatile(
        "mma.sync.aligned.m16n8k16.row.col.f32.bf16.bf16.f32 "
        "{%0,%1,%2,%3}, {%4,%5,%6,%7}, {%8,%9}, {%0,%1,%2,%3};\n"
        : "+f"(c[0]), "+f"(c[1]), "+f"(c[2]), "+f"(c[3])
        : "r"(a[0]), "r"(a[1]), "r"(a[2]), "r"(a[3]), "r"(b0), "r"(b1));
}

// split fp32 pair into bf16 hi + bf16 residual (packed b32 regs for MMA)
__device__ __forceinline__ void split_pack(float2 v, unsigned &hi, unsigned &lo) {
    __nv_bfloat162 h2 = __floats2bfloat162_rn(v.x, v.y);
    float2 hf = __bfloat1622float2(h2);
    __nv_bfloat162 l2 = __floats2bfloat162_rn(v.x - hf.x, v.y - hf.y);
    hi = *reinterpret_cast<unsigned*>(&h2);
    lo = *reinterpret_cast<unsigned*>(&l2);
}

__device__ __forceinline__ float elu(float v) {
    return v > 0.0f ? v : expm1f(v);
}

// ------------------------- prep: split + transpose weights -----------------
// g_WT_*[l][n*256 + k] = split( W_l[k][n] ) ; layer0 uses W1 rows 0..255.

__global__ void prep_weights_kernel(const float* __restrict__ W1,
                                    const float* __restrict__ W2,
                                    const float* __restrict__ W3) {
    int t = blockIdx.x * 256 + threadIdx.x;       // < 3*65536
    int l = t >> 16;
    int r = t & 65535;
    int n = r >> 8, k = r & 255;
    const float* W = (l == 0) ? W1 : (l == 1 ? W2 : W3);
    float w = W[k * H + n];
    __nv_bfloat16 h = __float2bfloat16_rn(w);
    g_WT_hi[t] = h;
    g_WT_lo[t] = __float2bfloat16_rn(w - __bfloat162float(h));
}

// ------------------------- zero init ---------------------------------------

__global__ void zero_out_kernel(float* __restrict__ out) {
    int i = blockIdx.x * 256 + threadIdx.x;       // < ATTR_OUT_F/4
    float4 z = make_float4(0.f, 0.f, 0.f, 0.f);
    *reinterpret_cast<float4*>(out + (size_t)i * 4) = z;
}

__global__ void zero_counts_kernel() {
    int i = blockIdx.x * 256 + threadIdx.x;       // < 262144
    g_ecnt[i] = 0;
    if (i < N_COARSE) g_ncnt[i] = 0;
}

// ------------------------- counts ------------------------------------------

__global__ void count_kernel(const int* __restrict__ f2c,
                             const int* __restrict__ f2ce) {
    int i = blockIdx.x * 256 + threadIdx.x;       // < E_FINE
    atomicAdd(&g_ecnt[f2ce[i]], 1);
    if (i < N_FINE) atomicAdd(&g_ncnt[f2c[i]], 1);
}

// ------------------------- edge scatter sum --------------------------------
// thread handles 8 contiguous floats of one fine edge row

__global__ void edge_scatter_kernel(const float* __restrict__ ea,
                                    const int* __restrict__ f2ce,
                                    float* __restrict__ out_edge) {
    int i = blockIdx.x * 256 + threadIdx.x;       // < E_FINE*32
    int row = i >> 5;
    int c   = (i & 31) * 8;
    int ce  = __ldg(f2ce + row);
    const float4* p = reinterpret_cast<const float4*>(ea + (size_t)row * H + c);
    float4 v0 = p[0], v1 = p[1];
    float* dst = out_edge + (size_t)ce * H + c;
    atomicAdd(dst + 0, v0.x); atomicAdd(dst + 1, v0.y);
    atomicAdd(dst + 2, v0.z); atomicAdd(dst + 3, v0.w);
    atomicAdd(dst + 4, v1.x); atomicAdd(dst + 5, v1.y);
    atomicAdd(dst + 6, v1.z); atomicAdd(dst + 7, v1.w);
}

// ------------------------- fused node MLP + residual + scatter -------------
// Block: 512 threads (16 warps as 4m x 4n), tile M=128, N=256, K streamed.
// SMEM: As fp32 [128][260] (x, then h1, then h2), B double-buffered bf16
// hi/lo transposed chunks [256 n][40 pitch] (k chunk = 32).

#define APITCH 260
#define BPITCH 40
#define AS_BYTES   (128 * APITCH * 4)                 // 133,120
#define BS_ELEMS_1 (H * BPITCH)                       // 10,240 bf16 per array
#define BS_BYTES   (2 * 2 * BS_ELEMS_1 * 2)           // 81,920
#define DS_OFF     (AS_BYTES + BS_BYTES)              // 215,040
#define F2C_OFF    (DS_OFF + 512)                     // 215,552
#define SMEM_BYTES (F2C_OFF + 512)                    // 216,064

__device__ __forceinline__ void loadB(__nv_bfloat16* Bs,
                                      const __nv_bfloat16* __restrict__ Wh,
                                      const __nv_bfloat16* __restrict__ Wl,
                                      int t, int buf, int k0) {
#pragma unroll
    for (int j = 0; j < 2; ++j) {
        int id  = t + j * 512;          // 0..1023
        int arr = id >> 9;              // 0 = hi, 1 = lo
        int rem = id & 511;
        int r = rem >> 1, hh = rem & 1; // row, 16-elem half
        const __nv_bfloat16* src = (arr ? Wl : Wh) + r * H + k0 + hh * 16;
        __nv_bfloat16* dst = Bs + buf * (2 * BS_ELEMS_1) + arr * BS_ELEMS_1
                             + r * BPITCH + hh * 16;
        uint4 v0 = *reinterpret_cast<const uint4*>(src);
        uint4 v1 = *reinterpret_cast<const uint4*>(src + 8);
        *reinterpret_cast<uint4*>(dst)     = v0;
        *reinterpret_cast<uint4*>(dst + 8) = v1;
    }
}

__global__ void __launch_bounds__(512, 1)
node_fused_kernel(const float* __restrict__ x,
                  const float* __restrict__ dist,
                  const int*   __restrict__ f2c,
                  const float* __restrict__ W1,   // for distance row (row 256)
                  const float* __restrict__ b1,
                  const float* __restrict__ b2,
                  const float* __restrict__ b3,
                  float* __restrict__ out_node) {
    extern __shared__ char sm[];
    float*         As   = reinterpret_cast<float*>(sm);
    __nv_bfloat16* Bs   = reinterpret_cast<__nv_bfloat16*>(sm + AS_BYTES);
    float*         ds   = reinterpret_cast<float*>(sm + DS_OFF);
    int*           f2cs = reinterpret_cast<int*>(sm + F2C_OFF);

    const int t = threadIdx.x;
    const int lane = t & 31, warp = t >> 5;
    const int g = lane >> 2, tg = lane & 3;
    const int wy = warp >> 2, wx = warp & 3;       // 4 x 4 warp grid
    const int m0 = blockIdx.x * 128;
    const float* w1last = W1 + H * H;              // distance weights row

    // load x tile into As (fp32)
    for (int i = t; i < 128 * 64; i += 512) {
        int r = i >> 6, c = (i & 63) << 2;
        float4 v = *reinterpret_cast<const float4*>(x + (size_t)(m0 + r) * H + c);
        float* d = As + r * APITCH + c;
        d[0] = v.x; d[1] = v.y; d[2] = v.z; d[3] = v.w;
    }
    if (t < 128) { ds[t] = dist[m0 + t]; f2cs[t] = f2c[m0 + t]; }

    float acc[2][8][4];

#pragma unroll 1
    for (int layer = 0; layer < 3; ++layer) {
#pragma unroll
        for (int a = 0; a < 2; ++a)
#pragma unroll
            for (int b = 0; b < 8; ++b)
#pragma unroll
                for (int q = 0; q < 4; ++q) acc[a][b][q] = 0.0f;

        const __nv_bfloat16* Wh = g_WT_hi + layer * (H * H);
        const __nv_bfloat16* Wl = g_WT_lo + layer * (H * H);

        loadB(Bs, Wh, Wl, t, 0, 0);
        __syncthreads();   // As ready (x load or previous epilogue) + chunk0 ready

#pragma unroll 1
        for (int c = 0; c < 8; ++c) {
            if (c < 7) loadB(Bs, Wh, Wl, t, (c + 1) & 1, (c + 1) * 32);

            const __nv_bfloat16* Bh = Bs + (c & 1) * (2 * BS_ELEMS_1);
#pragma unroll
            for (int ks = 0; ks < 32; ks += 16) {
                unsigned ah[2][4], al[2][4];
                const int kk = c * 32 + ks + 2 * tg;
#pragma unroll
                for (int mt = 0; mt < 2; ++mt) {
                    const float* ap = As + (wy * 32 + mt * 16 + g) * APITCH + kk;
                    split_pack(*reinterpret_cast<const float2*>(ap),              ah[mt][0], al[mt][0]);
                    split_pack(*reinterpret_cast<const float2*>(ap + 8 * APITCH), ah[mt][1], al[mt][1]);
                    split_pack(*reinterpret_cast<const float2*>(ap + 8),          ah[mt][2], al[mt][2]);
                    split_pack(*reinterpret_cast<const float2*>(ap + 8 * APITCH + 8), ah[mt][3], al[mt][3]);
                }
#pragma unroll
                for (int nt = 0; nt < 8; ++nt) {
                    const __nv_bfloat16* pb = Bh + (wx * 64 + nt * 8 + g) * BPITCH + ks + 2 * tg;
                    unsigned bh0 = *reinterpret_cast<const unsigned*>(pb);
                    unsigned bh1 = *reinterpret_cast<const unsigned*>(pb + 8);
                    unsigned bl0 = *reinterpret_cast<const unsigned*>(pb + BS_ELEMS_1);
                    unsigned bl1 = *reinterpret_cast<const unsigned*>(pb + BS_ELEMS_1 + 8);
#pragma unroll
                    for (int mt = 0; mt < 2; ++mt) {
                        mma16816(acc[mt][nt], ah[mt], bh0, bh1);  // hi*hi
                        mma16816(acc[mt][nt], ah[mt], bl0, bl1);  // hi*lo
                        mma16816(acc[mt][nt], al[mt], bh0, bh1);  // lo*hi
                    }
                }
            }
            __syncthreads();
        }

        // ---- epilogue ----
        const float* bias = (layer == 0) ? b1 : (layer == 1 ? b2 : b3);
#pragma unroll
        for (int mt = 0; mt < 2; ++mt) {
            const int r = wy * 32 + mt * 16 + g;
#pragma unroll
            for (int nt = 0; nt < 8; ++nt) {
                const int n = wx * 64 + nt * 8 + 2 * tg;
                float2 bv = *reinterpret_cast<const float2*>(bias + n);
                float v0 = acc[mt][nt][0] + bv.x;
                float v1 = acc[mt][nt][1] + bv.y;
                float v2 = acc[mt][nt][2] + bv.x;
                float v3 = acc[mt][nt][3] + bv.y;
                if (layer == 0) {   // distance rank-1 term of [x|d] @ W1
                    float2 wd = *reinterpret_cast<const float2*>(w1last + n);
                    v0 += ds[r] * wd.x;     v1 += ds[r] * wd.y;
                    v2 += ds[r + 8] * wd.x; v3 += ds[r + 8] * wd.y;
                }
                if (layer < 2) {
                    v0 = elu(v0); v1 = elu(v1); v2 = elu(v2); v3 = elu(v3);
                    *reinterpret_cast<float2*>(As + r * APITCH + n)       = make_float2(v0, v1);
                    *reinterpret_cast<float2*>(As + (r + 8) * APITCH + n) = make_float2(v2, v3);
                } else {
                    float2 x0 = *reinterpret_cast<const float2*>(x + (size_t)(m0 + r) * H + n);
                    float2 x1 = *reinterpret_cast<const float2*>(x + (size_t)(m0 + r + 8) * H + n);
                    v0 += x0.x; v1 += x0.y; v2 += x1.x; v3 += x1.y;
                    float* o0 = out_node + (size_t)f2cs[r] * H + n;
                    float* o1 = out_node + (size_t)f2cs[r + 8] * H + n;
                    atomicAdd(o0, v0);     atomicAdd(o0 + 1, v1);
                    atomicAdd(o1, v2);     atomicAdd(o1 + 1, v3);
                }
            }
        }
        // next layer's post-prefetch __syncthreads orders these As writes
        // against all warps' reads.
    }
}

// ------------------------- finalize: mean divide + index cast --------------

__global__ void finalize_kernel(float* __restrict__ out,
                                const int* __restrict__ cei) {
    int i = blockIdx.x * 256 + threadIdx.x;       // < ATTR_OUT_F/4
    size_t j = (size_t)i * 4;
    float inv;
    if (j < NODE_OUT_F) {
        inv = 1.0f / fmaxf((float)g_ncnt[j >> 8], 1.0f);
    } else {
        size_t jj = j - NODE_OUT_F;
        inv = 1.0f / fmaxf((float)g_ecnt[jj >> 8], 1.0f);
    }
    float4* p = reinterpret_cast<float4*>(out + j);
    float4 v = *p;
    v.x *= inv; v.y *= inv; v.z *= inv; v.w *= inv;
    *p = v;

    if (i < IDX_OUT_F / 4) {
        int4 e = *reinterpret_cast<const int4*>(cei + (size_t)i * 4);
        float4 f = make_float4((float)e.x, (float)e.y, (float)e.z, (float)e.w);
        *reinterpret_cast<float4*>(out + ATTR_OUT_F + (size_t)i * 4) = f;
    }
}

// ------------------------- launch ------------------------------------------

extern "C" void kernel_launch(void* const* d_in, const int* in_sizes, int n_in,
                              void* d_out, int out_size) {
    const float* x    = (const float*)d_in[0];
    const float* ea   = (const float*)d_in[1];
    const float* dist = (const float*)d_in[2];
    const int*   f2c  = (const int*)d_in[3];
    const int*   f2ce = (const int*)d_in[4];
    const int*   cei  = (const int*)d_in[5];
    const float* W1   = (const float*)d_in[6];
    const float* b1   = (const float*)d_in[7];
    const float* W2   = (const float*)d_in[8];
    const float* b2   = (const float*)d_in[9];
    const float* W3   = (const float*)d_in[10];
    const float* b3   = (const float*)d_in[11];

    float* out      = (float*)d_out;
    float* out_node = out;
    float* out_edge = out + NODE_OUT_F;

    cudaFuncSetAttribute(node_fused_kernel,
                         cudaFuncAttributeMaxDynamicSharedMemorySize, SMEM_BYTES);

    prep_weights_kernel<<<(3 * H * H) / 256, 256>>>(W1, W2, W3);
    zero_out_kernel<<<ATTR_OUT_F / 4 / 256, 256>>>(out);
    zero_counts_kernel<<<E_COARSE / 256, 256>>>();
    count_kernel<<<E_FINE / 256, 256>>>(f2c, f2ce);
    edge_scatter_kernel<<<(E_FINE * 32) / 256, 256>>>(ea, f2ce, out_edge);
    node_fused_kernel<<<N_FINE / 128, 512, SMEM_BYTES>>>(
        x, dist, f2c, W1, b1, b2, b3, out_node);
    finalize_kernel<<<ATTR_OUT_F / 4 / 256, 256>>>(out, cei);
}

// round 6
// speedup vs baseline: 1.0066x; 1.0066x over previous
#include <cuda_runtime.h>
#include <cuda_bf16.h>

// ---------------------------------------------------------------------------
// MultiscaleMessagePassing on GB300 (sm_103a)
//
// Outputs (concatenated float32 in d_out):
//   [0 .. 16,777,216)                 coarse_node_attrs  [65536, 256]
//   [16,777,216 .. 83,886,080)        coarse_edge_attrs  [262144, 256]
//   [83,886,080 .. 84,410,368)        coarse_edge_index  [2, 262144] (cast)
// ---------------------------------------------------------------------------

#define H         256
#define N_FINE    262144
#define E_FINE    524288
#define N_COARSE  65536
#define E_COARSE  262144

#define NODE_OUT_F   (N_COARSE * H)           // 16,777,216
#define EDGE_OUT_F   (E_COARSE * H)           // 67,108,864
#define ATTR_OUT_F   (NODE_OUT_F + EDGE_OUT_F) // 83,886,080
#define IDX_OUT_F    (2 * E_COARSE)           // 524,288

// scratch (device globals; no allocation)
__device__ __align__(16) __nv_bfloat16 g_WT_hi[3 * H * H];
__device__ __align__(16) __nv_bfloat16 g_WT_lo[3 * H * H];
__device__ int g_ncnt[N_COARSE];
__device__ int g_ecnt[E_COARSE];

// ------------------------- small helpers -----------------------------------

__device__ __forceinline__ void mma16816(float c[4], const unsigned a[4],
                                         unsigned b0, unsigned b1) {
    asm volatile(
        "mma.sync.aligned.m16n8k16.row.col.f32.bf16.bf16.f32 "
        "{%0,%1,%2,%3}, {%4,%5,%6,%7}, {%8,%9}, {%0,%1,%2,%3};\n"
        : "+f"(c[0]), "+f"(c[1]), "+f"(c[2]), "+f"(c[3])
        : "r"(a[0]), "r"(a[1]), "r"(a[2]), "r"(a[3]), "r"(b0), "r"(b1));
}

// split fp32 pair into bf16 hi + bf16 residual (packed b32 regs for MMA)
__device__ __forceinline__ void split_pack(float2 v, unsigned &hi, unsigned &lo) {
    __nv_bfloat162 h2 = __floats2bfloat162_rn(v.x, v.y);
    float2 hf = __bfloat1622float2(h2);
    __nv_bfloat162 l2 = __floats2bfloat162_rn(v.x - hf.x, v.y - hf.y);
    hi = *reinterpret_cast<unsigned*>(&h2);
    lo = *reinterpret_cast<unsigned*>(&l2);
}

__device__ __forceinline__ float elu(float v) {
    return v > 0.0f ? v : expm1f(v);
}

// ------------------------- prep: split + transpose weights -----------------
// g_WT_*[l][n*256 + k] = split( W_l[k][n] ) ; layer0 uses W1 rows 0..255.

__global__ void prep_weights_kernel(const float* __restrict__ W1,
                                    const float* __restrict__ W2,
                                    const float* __restrict__ W3) {
    int t = blockIdx.x * 256 + threadIdx.x;       // < 3*65536
    int l = t >> 16;
    int r = t & 65535;
    int n = r >> 8, k = r & 255;
    const float* W = (l == 0) ? W1 : (l == 1 ? W2 : W3);
    float w = W[k * H + n];
    __nv_bfloat16 h = __float2bfloat16_rn(w);
    g_WT_hi[t] = h;
    g_WT_lo[t] = __float2bfloat16_rn(w - __bfloat162float(h));
}

// ------------------------- zero init ---------------------------------------

__global__ void zero_out_kernel(float* __restrict__ out) {
    int i = blockIdx.x * 256 + threadIdx.x;       // < ATTR_OUT_F/4
    float4 z = make_float4(0.f, 0.f, 0.f, 0.f);
    *reinterpret_cast<float4*>(out + (size_t)i * 4) = z;
}

__global__ void zero_counts_kernel() {
    int i = blockIdx.x * 256 + threadIdx.x;       // < 262144
    g_ecnt[i] = 0;
    if (i < N_COARSE) g_ncnt[i] = 0;
}

// ------------------------- counts ------------------------------------------

__global__ void count_kernel(const int* __restrict__ f2c,
                             const int* __restrict__ f2ce) {
    int i = blockIdx.x * 256 + threadIdx.x;       // < E_FINE
    atomicAdd(&g_ecnt[f2ce[i]], 1);
    if (i < N_FINE) atomicAdd(&g_ncnt[f2c[i]], 1);
}

// ------------------------- edge scatter sum --------------------------------
// thread handles 8 contiguous floats of one fine edge row

__global__ void edge_scatter_kernel(const float* __restrict__ ea,
                                    const int* __restrict__ f2ce,
                                    float* __restrict__ out_edge) {
    int i = blockIdx.x * 256 + threadIdx.x;       // < E_FINE*32
    int row = i >> 5;
    int c   = (i & 31) * 8;
    int ce  = __ldg(f2ce + row);
    const float4* p = reinterpret_cast<const float4*>(ea + (size_t)row * H + c);
    float4 v0 = p[0], v1 = p[1];
    float* dst = out_edge + (size_t)ce * H + c;
    atomicAdd(dst + 0, v0.x); atomicAdd(dst + 1, v0.y);
    atomicAdd(dst + 2, v0.z); atomicAdd(dst + 3, v0.w);
    atomicAdd(dst + 4, v1.x); atomicAdd(dst + 5, v1.y);
    atomicAdd(dst + 6, v1.z); atomicAdd(dst + 7, v1.w);
}

// ------------------------- fused node MLP + residual + scatter -------------
// Block: 512 threads (16 warps as 4m x 4n), tile M=128, N=256, K streamed.
// SMEM: As fp32 [128][260] (x, then h1, then h2), B double-buffered bf16
// hi/lo transposed chunks [256 n][40 pitch] (k chunk = 32).

#define APITCH 260
#define BPITCH 40
#define AS_BYTES   (128 * APITCH * 4)                 // 133,120
#define BS_ELEMS_1 (H * BPITCH)                       // 10,240 bf16 per array
#define BS_BYTES   (2 * 2 * BS_ELEMS_1 * 2)           // 81,920
#define DS_OFF     (AS_BYTES + BS_BYTES)              // 215,040
#define F2C_OFF    (DS_OFF + 512)                     // 215,552
#define SMEM_BYTES (F2C_OFF + 512)                    // 216,064

__device__ __forceinline__ void loadB(__nv_bfloat16* Bs,
                                      const __nv_bfloat16* __restrict__ Wh,
                                      const __nv_bfloat16* __restrict__ Wl,
                                      int t, int buf, int k0) {
#pragma unroll
    for (int j = 0; j < 2; ++j) {
        int id  = t + j * 512;          // 0..1023
        int arr = id >> 9;              // 0 = hi, 1 = lo
        int rem = id & 511;
        int r = rem >> 1, hh = rem & 1; // row, 16-elem half
        const __nv_bfloat16* src = (arr ? Wl : Wh) + r * H + k0 + hh * 16;
        __nv_bfloat16* dst = Bs + buf * (2 * BS_ELEMS_1) + arr * BS_ELEMS_1
                             + r * BPITCH + hh * 16;
        uint4 v0 = *reinterpret_cast<const uint4*>(src);
        uint4 v1 = *reinterpret_cast<const uint4*>(src + 8);
        *reinterpret_cast<uint4*>(dst)     = v0;
        *reinterpret_cast<uint4*>(dst + 8) = v1;
    }
}

__global__ void __launch_bounds__(512, 1)
node_fused_kernel(const float* __restrict__ x,
                  const float* __restrict__ dist,
                  const int*   __restrict__ f2c,
                  const float* __restrict__ W1,   // for distance row (row 256)
                  const float* __restrict__ b1,
                  const float* __restrict__ b2,
                  const float* __restrict__ b3,
                  float* __restrict__ out_node) {
    extern __shared__ char sm[];
    float*         As   = reinterpret_cast<float*>(sm);
    __nv_bfloat16* Bs   = reinterpret_cast<__nv_bfloat16*>(sm + AS_BYTES);
    float*         ds   = reinterpret_cast<float*>(sm + DS_OFF);
    int*           f2cs = reinterpret_cast<int*>(sm + F2C_OFF);

    const int t = threadIdx.x;
    const int lane = t & 31, warp = t >> 5;
    const int g = lane >> 2, tg = lane & 3;
    const int wy = warp >> 2, wx = warp & 3;       // 4 x 4 warp grid
    const int m0 = blockIdx.x * 128;
    const float* w1last = W1 + H * H;              // distance weights row

    // load x tile into As (fp32)
    for (int i = t; i < 128 * 64; i += 512) {
        int r = i >> 6, c = (i & 63) << 2;
        float4 v = *reinterpret_cast<const float4*>(x + (size_t)(m0 + r) * H + c);
        float* d = As + r * APITCH + c;
        d[0] = v.x; d[1] = v.y; d[2] = v.z; d[3] = v.w;
    }
    if (t < 128) { ds[t] = dist[m0 + t]; f2cs[t] = f2c[m0 + t]; }

    float acc[2][8][4];

#pragma unroll 1
    for (int layer = 0; layer < 3; ++layer) {
#pragma unroll
        for (int a = 0; a < 2; ++a)
#pragma unroll
            for (int b = 0; b < 8; ++b)
#pragma unroll
                for (int q = 0; q < 4; ++q) acc[a][b][q] = 0.0f;

        const __nv_bfloat16* Wh = g_WT_hi + layer * (H * H);
        const __nv_bfloat16* Wl = g_WT_lo + layer * (H * H);

        loadB(Bs, Wh, Wl, t, 0, 0);
        __syncthreads();   // As ready (x load or previous epilogue) + chunk0 ready

#pragma unroll 1
        for (int c = 0; c < 8; ++c) {
            if (c < 7) loadB(Bs, Wh, Wl, t, (c + 1) & 1, (c + 1) * 32);

            const __nv_bfloat16* Bh = Bs + (c & 1) * (2 * BS_ELEMS_1);
#pragma unroll
            for (int ks = 0; ks < 32; ks += 16) {
                unsigned ah[2][4], al[2][4];
                const int kk = c * 32 + ks + 2 * tg;
#pragma unroll
                for (int mt = 0; mt < 2; ++mt) {
                    const float* ap = As + (wy * 32 + mt * 16 + g) * APITCH + kk;
                    split_pack(*reinterpret_cast<const float2*>(ap),              ah[mt][0], al[mt][0]);
                    split_pack(*reinterpret_cast<const float2*>(ap + 8 * APITCH), ah[mt][1], al[mt][1]);
                    split_pack(*reinterpret_cast<const float2*>(ap + 8),          ah[mt][2], al[mt][2]);
                    split_pack(*reinterpret_cast<const float2*>(ap + 8 * APITCH + 8), ah[mt][3], al[mt][3]);
                }
#pragma unroll
                for (int nt = 0; nt < 8; ++nt) {
                    const __nv_bfloat16* pb = Bh + (wx * 64 + nt * 8 + g) * BPITCH + ks + 2 * tg;
                    unsigned bh0 = *reinterpret_cast<const unsigned*>(pb);
                    unsigned bh1 = *reinterpret_cast<const unsigned*>(pb + 8);
                    unsigned bl0 = *reinterpret_cast<const unsigned*>(pb + BS_ELEMS_1);
                    unsigned bl1 = *reinterpret_cast<const unsigned*>(pb + BS_ELEMS_1 + 8);
#pragma unroll
                    for (int mt = 0; mt < 2; ++mt) {
                        mma16816(acc[mt][nt], ah[mt], bh0, bh1);  // hi*hi
                        mma16816(acc[mt][nt], ah[mt], bl0, bl1);  // hi*lo
                        mma16816(acc[mt][nt], al[mt], bh0, bh1);  // lo*hi
                    }
                }
            }
            __syncthreads();
        }

        // ---- epilogue ----
        const float* bias = (layer == 0) ? b1 : (layer == 1 ? b2 : b3);
#pragma unroll
        for (int mt = 0; mt < 2; ++mt) {
            const int r = wy * 32 + mt * 16 + g;
#pragma unroll
            for (int nt = 0; nt < 8; ++nt) {
                const int n = wx * 64 + nt * 8 + 2 * tg;
                float2 bv = *reinterpret_cast<const float2*>(bias + n);
                float v0 = acc[mt][nt][0] + bv.x;
                float v1 = acc[mt][nt][1] + bv.y;
                float v2 = acc[mt][nt][2] + bv.x;
                float v3 = acc[mt][nt][3] + bv.y;
                if (layer == 0) {   // distance rank-1 term of [x|d] @ W1
                    float2 wd = *reinterpret_cast<const float2*>(w1last + n);
                    v0 += ds[r] * wd.x;     v1 += ds[r] * wd.y;
                    v2 += ds[r + 8] * wd.x; v3 += ds[r + 8] * wd.y;
                }
                if (layer < 2) {
                    v0 = elu(v0); v1 = elu(v1); v2 = elu(v2); v3 = elu(v3);
                    *reinterpret_cast<float2*>(As + r * APITCH + n)       = make_float2(v0, v1);
                    *reinterpret_cast<float2*>(As + (r + 8) * APITCH + n) = make_float2(v2, v3);
                } else {
                    float2 x0 = *reinterpret_cast<const float2*>(x + (size_t)(m0 + r) * H + n);
                    float2 x1 = *reinterpret_cast<const float2*>(x + (size_t)(m0 + r + 8) * H + n);
                    v0 += x0.x; v1 += x0.y; v2 += x1.x; v3 += x1.y;
                    float* o0 = out_node + (size_t)f2cs[r] * H + n;
                    float* o1 = out_node + (size_t)f2cs[r + 8] * H + n;
                    atomicAdd(o0, v0);     atomicAdd(o0 + 1, v1);
                    atomicAdd(o1, v2);     atomicAdd(o1 + 1, v3);
                }
            }
        }
        // next layer's post-prefetch __syncthreads orders these As writes
        // against all warps' reads.
    }
}

// ------------------------- finalize: mean divide + index cast --------------

__global__ void finalize_kernel(float* __restrict__ out,
                                const int* __restrict__ cei) {
    int i = blockIdx.x * 256 + threadIdx.x;       // < ATTR_OUT_F/4
    size_t j = (size_t)i * 4;
    float inv;
    if (j < NODE_OUT_F) {
        inv = 1.0f / fmaxf((float)g_ncnt[j >> 8], 1.0f);
    } else {
        size_t jj = j - NODE_OUT_F;
        inv = 1.0f / fmaxf((float)g_ecnt[jj >> 8], 1.0f);
    }
    float4* p = reinterpret_cast<float4*>(out + j);
    float4 v = *p;
    v.x *= inv; v.y *= inv; v.z *= inv; v.w *= inv;
    *p = v;

    if (i < IDX_OUT_F / 4) {
        int4 e = *reinterpret_cast<const int4*>(cei + (size_t)i * 4);
        float4 f = make_float4((float)e.x, (float)e.y, (float)e.z, (float)e.w);
        *reinterpret_cast<float4*>(out + ATTR_OUT_F + (size_t)i * 4) = f;
    }
}

// ------------------------- launch ------------------------------------------

extern "C" void kernel_launch(void* const* d_in, const int* in_sizes, int n_in,
                              void* d_out, int out_size) {
    const float* x    = (const float*)d_in[0];
    const float* ea   = (const float*)d_in[1];
    const float* dist = (const float*)d_in[2];
    const int*   f2c  = (const int*)d_in[3];
    const int*   f2ce = (const int*)d_in[4];
    const int*   cei  = (const int*)d_in[5];
    const float* W1   = (const float*)d_in[6];
    const float* b1   = (const float*)d_in[7];
    const float* W2   = (const float*)d_in[8];
    const float* b2   = (const float*)d_in[9];
    const float* W3   = (const float*)d_in[10];
    const float* b3   = (const float*)d_in[11];

    float* out      = (float*)d_out;
    float* out_node = out;
    float* out_edge = out + NODE_OUT_F;

    cudaFuncSetAttribute(node_fused_kernel,
                         cudaFuncAttributeMaxDynamicSharedMemorySize, SMEM_BYTES);

    prep_weights_kernel<<<(3 * H * H) / 256, 256>>>(W1, W2, W3);
    zero_out_kernel<<<ATTR_OUT_F / 4 / 256, 256>>>(out);
    zero_counts_kernel<<<E_COARSE / 256, 256>>>();
    count_kernel<<<E_FINE / 256, 256>>>(f2c, f2ce);
    edge_scatter_kernel<<<(E_FINE * 32) / 256, 256>>>(ea, f2ce, out_edge);
    node_fused_kernel<<<N_FINE / 128, 512, SMEM_BYTES>>>(
        x, dist, f2c, W1, b1, b2, b3, out_node);
    finalize_kernel<<<ATTR_OUT_F / 4 / 256, 256>>>(out, cei);
}

// round 7
// speedup vs baseline: 1.3663x; 1.3573x over previous
#include <cuda_runtime.h>
#include <cuda_bf16.h>

// ---------------------------------------------------------------------------
// MultiscaleMessagePassing on GB300 (sm_103a) — R6: scatter -> CSR gather
//
// Outputs (concatenated float32 in d_out):
//   [0 .. 16,777,216)                 coarse_node_attrs  [65536, 256]
//   [16,777,216 .. 83,886,080)        coarse_edge_attrs  [262144, 256]
//   [83,886,080 .. 84,410,368)        coarse_edge_index  [2, 262144] (cast)
// ---------------------------------------------------------------------------

#define H         256
#define N_FINE    262144
#define E_FINE    524288
#define N_COARSE  65536
#define E_COARSE  262144

#define NODE_OUT_F   (N_COARSE * H)            // 16,777,216
#define EDGE_OUT_F   (E_COARSE * H)            // 67,108,864
#define ATTR_OUT_F   (NODE_OUT_F + EDGE_OUT_F) // 83,886,080
#define IDX_OUT_F    (2 * E_COARSE)            // 524,288

// ----- scratch (device globals; no allocation) ------------------------------
__device__ __align__(16) __nv_bfloat16 g_WT_hi[3 * H * H];
__device__ __align__(16) __nv_bfloat16 g_WT_lo[3 * H * H];
__device__ int g_ncnt[N_COARSE];
__device__ int g_ecnt[E_COARSE];
__device__ int g_noff[N_COARSE], g_ncur[N_COARSE];
__device__ int g_eoff[E_COARSE], g_ecur[E_COARSE];
__device__ int g_nperm[N_FINE];
__device__ int g_eperm[E_FINE];
__device__ int g_blk[256];
__device__ __align__(16) float g_fnp[(size_t)N_FINE * H];   // 256 MB staging

// ------------------------- small helpers -----------------------------------

__device__ __forceinline__ void mma16816(float c[4], const unsigned a[4],
                                         unsigned b0, unsigned b1) {
    asm volatile(
        "mma.sync.aligned.m16n8k16.row.col.f32.bf16.bf16.f32 "
        "{%0,%1,%2,%3}, {%4,%5,%6,%7}, {%8,%9}, {%0,%1,%2,%3};\n"
        : "+f"(c[0]), "+f"(c[1]), "+f"(c[2]), "+f"(c[3])
        : "r"(a[0]), "r"(a[1]), "r"(a[2]), "r"(a[3]), "r"(b0), "r"(b1));
}

__device__ __forceinline__ void split_pack(float2 v, unsigned &hi, unsigned &lo) {
    __nv_bfloat162 h2 = __floats2bfloat162_rn(v.x, v.y);
    float2 hf = __bfloat1622float2(h2);
    __nv_bfloat162 l2 = __floats2bfloat162_rn(v.x - hf.x, v.y - hf.y);
    hi = *reinterpret_cast<unsigned*>(&h2);
    lo = *reinterpret_cast<unsigned*>(&l2);
}

__device__ __forceinline__ float elu(float v) {
    return v > 0.0f ? v : expm1f(v);
}

// ------------------------- prep: split + transpose weights -----------------

__global__ void prep_weights_kernel(const float* __restrict__ W1,
                                    const float* __restrict__ W2,
                                    const float* __restrict__ W3) {
    int t = blockIdx.x * 256 + threadIdx.x;       // < 3*65536
    int l = t >> 16;
    int r = t & 65535;
    int n = r >> 8, k = r & 255;
    const float* W = (l == 0) ? W1 : (l == 1 ? W2 : W3);
    float w = W[k * H + n];
    __nv_bfloat16 h = __float2bfloat16_rn(w);
    g_WT_hi[t] = h;
    g_WT_lo[t] = __float2bfloat16_rn(w - __bfloat162float(h));
}

// ------------------------- counts ------------------------------------------

__global__ void zero_counts_kernel() {
    int i = blockIdx.x * 256 + threadIdx.x;       // < E_COARSE
    g_ecnt[i] = 0;
    if (i < N_COARSE) g_ncnt[i] = 0;
}

__global__ void count_kernel(const int* __restrict__ f2c,
                             const int* __restrict__ f2ce) {
    int i = blockIdx.x * 256 + threadIdx.x;       // < E_FINE
    atomicAdd(&g_ecnt[f2ce[i]], 1);
    if (i < N_FINE) atomicAdd(&g_ncnt[f2c[i]], 1);
}

// ------------------------- CSR build: scan + bucket fill --------------------
// which: 0 = edges (262144), 1 = nodes (65536)

__global__ void scan_block_kernel(int which) {
    __shared__ int s[1024];
    const int* cnt = which ? g_ncnt : g_ecnt;
    int*       out = which ? g_noff : g_eoff;
    int t   = threadIdx.x;
    int gid = blockIdx.x * 1024 + t;
    int v = cnt[gid];
    s[t] = v;
    __syncthreads();
#pragma unroll
    for (int off = 1; off < 1024; off <<= 1) {
        int xv = (t >= off) ? s[t - off] : 0;
        __syncthreads();
        s[t] += xv;
        __syncthreads();
    }
    out[gid] = s[t] - v;                          // exclusive within block
    if (t == 1023) g_blk[blockIdx.x] = s[t];
}

__global__ void scan_tops_kernel(int nb) {        // single block, nb <= 256
    __shared__ int s[256];
    int t = threadIdx.x;
    int v = (t < nb) ? g_blk[t] : 0;
    s[t] = v;
    __syncthreads();
#pragma unroll
    for (int off = 1; off < 256; off <<= 1) {
        int xv = (t >= off) ? s[t - off] : 0;
        __syncthreads();
        s[t] += xv;
        __syncthreads();
    }
    if (t < nb) g_blk[t] = s[t] - v;              // exclusive
}

__global__ void scan_add_kernel(int which) {
    int gid = blockIdx.x * 256 + threadIdx.x;
    int* out = which ? g_noff : g_eoff;
    int* cur = which ? g_ncur : g_ecur;
    int v = out[gid] + g_blk[gid >> 10];
    out[gid] = v;
    cur[gid] = v;                                 // mutable cursor copy
}

__global__ void fill_perm_kernel(const int* __restrict__ f2c,
                                 const int* __restrict__ f2ce) {
    int i = blockIdx.x * 256 + threadIdx.x;       // < E_FINE
    int ce = f2ce[i];
    int p = atomicAdd(&g_ecur[ce], 1);
    g_eperm[p] = i;
    if (i < N_FINE) {
        int cn = f2c[i];
        int q = atomicAdd(&g_ncur[cn], 1);
        g_nperm[q] = i;
    }
}

// ------------------------- gather (sum + mean, single write) ---------------

__global__ void edge_gather_kernel(const float* __restrict__ ea,
                                   float* __restrict__ out_edge) {
    int t  = blockIdx.x * 256 + threadIdx.x;      // < E_COARSE*64
    int ce = t >> 6;
    int c  = (t & 63) * 4;
    int start = g_eoff[ce];
    int deg   = g_ecnt[ce];
    float4 s = make_float4(0.f, 0.f, 0.f, 0.f);
    for (int j = 0; j < deg; ++j) {
        int row = g_eperm[start + j];
        float4 v = *reinterpret_cast<const float4*>(ea + (size_t)row * H + c);
        s.x += v.x; s.y += v.y; s.z += v.z; s.w += v.w;
    }
    float inv = 1.0f / fmaxf((float)deg, 1.0f);
    s.x *= inv; s.y *= inv; s.z *= inv; s.w *= inv;
    *reinterpret_cast<float4*>(out_edge + (size_t)ce * H + c) = s;
}

__global__ void node_gather_kernel(float* __restrict__ out_node) {
    int t  = blockIdx.x * 256 + threadIdx.x;      // < N_COARSE*64
    int cn = t >> 6;
    int c  = (t & 63) * 4;
    int start = g_noff[cn];
    int deg   = g_ncnt[cn];
    float4 s = make_float4(0.f, 0.f, 0.f, 0.f);
    for (int j = 0; j < deg; ++j) {
        int row = g_nperm[start + j];
        float4 v = *reinterpret_cast<const float4*>(g_fnp + (size_t)row * H + c);
        s.x += v.x; s.y += v.y; s.z += v.z; s.w += v.w;
    }
    float inv = 1.0f / fmaxf((float)deg, 1.0f);
    s.x *= inv; s.y *= inv; s.z *= inv; s.w *= inv;
    *reinterpret_cast<float4*>(out_node + (size_t)cn * H + c) = s;
}

// ------------------------- fused node MLP (writes g_fnp) -------------------

#define APITCH 260
#define BPITCH 40
#define AS_BYTES   (128 * APITCH * 4)                 // 133,120
#define BS_ELEMS_1 (H * BPITCH)                       // 10,240 bf16 per array
#define BS_BYTES   (2 * 2 * BS_ELEMS_1 * 2)           // 81,920
#define DS_OFF     (AS_BYTES + BS_BYTES)              // 215,040
#define SMEM_BYTES (DS_OFF + 512)                     // 215,552

__device__ __forceinline__ void loadB(__nv_bfloat16* Bs,
                                      const __nv_bfloat16* __restrict__ Wh,
                                      const __nv_bfloat16* __restrict__ Wl,
                                      int t, int buf, int k0) {
#pragma unroll
    for (int j = 0; j < 2; ++j) {
        int id  = t + j * 512;          // 0..1023
        int arr = id >> 9;              // 0 = hi, 1 = lo
        int rem = id & 511;
        int r = rem >> 1, hh = rem & 1;
        const __nv_bfloat16* src = (arr ? Wl : Wh) + r * H + k0 + hh * 16;
        __nv_bfloat16* dst = Bs + buf * (2 * BS_ELEMS_1) + arr * BS_ELEMS_1
                             + r * BPITCH + hh * 16;
        uint4 v0 = *reinterpret_cast<const uint4*>(src);
        uint4 v1 = *reinterpret_cast<const uint4*>(src + 8);
        *reinterpret_cast<uint4*>(dst)     = v0;
        *reinterpret_cast<uint4*>(dst + 8) = v1;
    }
}

__global__ void __launch_bounds__(512, 1)
node_fused_kernel(const float* __restrict__ x,
                  const float* __restrict__ dist,
                  const float* __restrict__ W1,   // distance row (row 256)
                  const float* __restrict__ b1,
                  const float* __restrict__ b2,
                  const float* __restrict__ b3) {
    extern __shared__ char sm[];
    float*         As = reinterpret_cast<float*>(sm);
    __nv_bfloat16* Bs = reinterpret_cast<__nv_bfloat16*>(sm + AS_BYTES);
    float*         ds = reinterpret_cast<float*>(sm + DS_OFF);

    const int t = threadIdx.x;
    const int lane = t & 31, warp = t >> 5;
    const int g = lane >> 2, tg = lane & 3;
    const int wy = warp >> 2, wx = warp & 3;
    const int m0 = blockIdx.x * 128;
    const float* w1last = W1 + H * H;

    for (int i = t; i < 128 * 64; i += 512) {
        int r = i >> 6, c = (i & 63) << 2;
        float4 v = *reinterpret_cast<const float4*>(x + (size_t)(m0 + r) * H + c);
        float* d = As + r * APITCH + c;
        d[0] = v.x; d[1] = v.y; d[2] = v.z; d[3] = v.w;
    }
    if (t < 128) ds[t] = dist[m0 + t];

    float acc[2][8][4];

#pragma unroll 1
    for (int layer = 0; layer < 3; ++layer) {
#pragma unroll
        for (int a = 0; a < 2; ++a)
#pragma unroll
            for (int b = 0; b < 8; ++b)
#pragma unroll
                for (int q = 0; q < 4; ++q) acc[a][b][q] = 0.0f;

        const __nv_bfloat16* Wh = g_WT_hi + layer * (H * H);
        const __nv_bfloat16* Wl = g_WT_lo + layer * (H * H);

        loadB(Bs, Wh, Wl, t, 0, 0);
        __syncthreads();

#pragma unroll 1
        for (int c = 0; c < 8; ++c) {
            if (c < 7) loadB(Bs, Wh, Wl, t, (c + 1) & 1, (c + 1) * 32);

            const __nv_bfloat16* Bh = Bs + (c & 1) * (2 * BS_ELEMS_1);
#pragma unroll
            for (int ks = 0; ks < 32; ks += 16) {
                unsigned ah[2][4], al[2][4];
                const int kk = c * 32 + ks + 2 * tg;
#pragma unroll
                for (int mt = 0; mt < 2; ++mt) {
                    const float* ap = As + (wy * 32 + mt * 16 + g) * APITCH + kk;
                    split_pack(*reinterpret_cast<const float2*>(ap),                  ah[mt][0], al[mt][0]);
                    split_pack(*reinterpret_cast<const float2*>(ap + 8 * APITCH),     ah[mt][1], al[mt][1]);
                    split_pack(*reinterpret_cast<const float2*>(ap + 8),              ah[mt][2], al[mt][2]);
                    split_pack(*reinterpret_cast<const float2*>(ap + 8 * APITCH + 8), ah[mt][3], al[mt][3]);
                }
#pragma unroll
                for (int nt = 0; nt < 8; ++nt) {
                    const __nv_bfloat16* pb = Bh + (wx * 64 + nt * 8 + g) * BPITCH + ks + 2 * tg;
                    unsigned bh0 = *reinterpret_cast<const unsigned*>(pb);
                    unsigned bh1 = *reinterpret_cast<const unsigned*>(pb + 8);
                    unsigned bl0 = *reinterpret_cast<const unsigned*>(pb + BS_ELEMS_1);
                    unsigned bl1 = *reinterpret_cast<const unsigned*>(pb + BS_ELEMS_1 + 8);
#pragma unroll
                    for (int mt = 0; mt < 2; ++mt) {
                        mma16816(acc[mt][nt], ah[mt], bh0, bh1);  // hi*hi
                        mma16816(acc[mt][nt], ah[mt], bl0, bl1);  // hi*lo
                        mma16816(acc[mt][nt], al[mt], bh0, bh1);  // lo*hi
                    }
                }
            }
            __syncthreads();
        }

        // ---- epilogue ----
        const float* bias = (layer == 0) ? b1 : (layer == 1 ? b2 : b3);
#pragma unroll
        for (int mt = 0; mt < 2; ++mt) {
            const int r = wy * 32 + mt * 16 + g;
#pragma unroll
            for (int nt = 0; nt < 8; ++nt) {
                const int n = wx * 64 + nt * 8 + 2 * tg;
                float2 bv = *reinterpret_cast<const float2*>(bias + n);
                float v0 = acc[mt][nt][0] + bv.x;
                float v1 = acc[mt][nt][1] + bv.y;
                float v2 = acc[mt][nt][2] + bv.x;
                float v3 = acc[mt][nt][3] + bv.y;
                if (layer == 0) {   // distance rank-1 term of [x|d] @ W1
                    float2 wd = *reinterpret_cast<const float2*>(w1last + n);
                    v0 += ds[r] * wd.x;     v1 += ds[r] * wd.y;
                    v2 += ds[r + 8] * wd.x; v3 += ds[r + 8] * wd.y;
                }
                if (layer < 2) {
                    v0 = elu(v0); v1 = elu(v1); v2 = elu(v2); v3 = elu(v3);
                    *reinterpret_cast<float2*>(As + r * APITCH + n)       = make_float2(v0, v1);
                    *reinterpret_cast<float2*>(As + (r + 8) * APITCH + n) = make_float2(v2, v3);
                } else {
                    float2 x0 = *reinterpret_cast<const float2*>(x + (size_t)(m0 + r) * H + n);
                    float2 x1 = *reinterpret_cast<const float2*>(x + (size_t)(m0 + r + 8) * H + n);
                    v0 += x0.x; v1 += x0.y; v2 += x1.x; v3 += x1.y;
                    *reinterpret_cast<float2*>(g_fnp + (size_t)(m0 + r) * H + n)     = make_float2(v0, v1);
                    *reinterpret_cast<float2*>(g_fnp + (size_t)(m0 + r + 8) * H + n) = make_float2(v2, v3);
                }
            }
        }
        // next layer's post-prefetch __syncthreads orders As writes vs reads
    }
}

// ------------------------- index cast ---------------------------------------

__global__ void idx_cast_kernel(const int* __restrict__ cei,
                                float* __restrict__ out_idx) {
    int i = blockIdx.x * 256 + threadIdx.x;       // < IDX_OUT_F/4
    int4 e = *reinterpret_cast<const int4*>(cei + (size_t)i * 4);
    float4 f = make_float4((float)e.x, (float)e.y, (float)e.z, (float)e.w);
    *reinterpret_cast<float4*>(out_idx + (size_t)i * 4) = f;
}

// ------------------------- launch ------------------------------------------

extern "C" void kernel_launch(void* const* d_in, const int* in_sizes, int n_in,
                              void* d_out, int out_size) {
    const float* x    = (const float*)d_in[0];
    const float* ea   = (const float*)d_in[1];
    const float* dist = (const float*)d_in[2];
    const int*   f2c  = (const int*)d_in[3];
    const int*   f2ce = (const int*)d_in[4];
    const int*   cei  = (const int*)d_in[5];
    const float* W1   = (const float*)d_in[6];
    const float* b1   = (const float*)d_in[7];
    const float* W2   = (const float*)d_in[8];
    const float* b2   = (const float*)d_in[9];
    const float* W3   = (const float*)d_in[10];
    const float* b3   = (const float*)d_in[11];

    float* out      = (float*)d_out;
    float* out_node = out;
    float* out_edge = out + NODE_OUT_F;
    float* out_idx  = out + ATTR_OUT_F;

    cudaFuncSetAttribute(node_fused_kernel,
                         cudaFuncAttributeMaxDynamicSharedMemorySize, SMEM_BYTES);

    prep_weights_kernel<<<(3 * H * H) / 256, 256>>>(W1, W2, W3);
    zero_counts_kernel<<<E_COARSE / 256, 256>>>();
    count_kernel<<<E_FINE / 256, 256>>>(f2c, f2ce);

    // edge CSR
    scan_block_kernel<<<E_COARSE / 1024, 1024>>>(0);
    scan_tops_kernel<<<1, 256>>>(E_COARSE / 1024);
    scan_add_kernel<<<E_COARSE / 256, 256>>>(0);
    // node CSR (reuses g_blk after edge scan completes; stream-ordered)
    scan_block_kernel<<<N_COARSE / 1024, 1024>>>(1);
    scan_tops_kernel<<<1, 256>>>(N_COARSE / 1024);
    scan_add_kernel<<<N_COARSE / 256, 256>>>(1);

    fill_perm_kernel<<<E_FINE / 256, 256>>>(f2c, f2ce);

    edge_gather_kernel<<<(E_COARSE * 64) / 256, 256>>>(ea, out_edge);

    node_fused_kernel<<<N_FINE / 128, 512, SMEM_BYTES>>>(
        x, dist, W1, b1, b2, b3);
    node_gather_kernel<<<(N_COARSE * 64) / 256, 256>>>(out_node);

    idx_cast_kernel<<<(IDX_OUT_F / 4) / 256, 256>>>(cei, out_idx);
}

// round 11
// speedup vs baseline: 1.6850x; 1.2333x over previous
#include <cuda_runtime.h>
#include <cuda_bf16.h>
#include <cuda_fp16.h>
#include <cstdint>

// ---------------------------------------------------------------------------
// MultiscaleMessagePassing on GB300 (sm_103 target — no tcgen05 available)
// R10: R6 proven structure; node MLP numeric scheme switched from bf16
//      3-term splitting to fp16 2-term splitting (A split hi/lo, B single
//      fp16). 48 -> 32 HMMA per warp-kstep.
//
// Outputs (concatenated float32 in d_out):
//   [0 .. 16,777,216)                 coarse_node_attrs  [65536, 256]
//   [16,777,216 .. 83,886,080)        coarse_edge_attrs  [262144, 256]
//   [83,886,080 .. 84,410,368)        coarse_edge_index  [2, 262144] (cast)
// ---------------------------------------------------------------------------

#define H         256
#define N_FINE    262144
#define E_FINE    524288
#define N_COARSE  65536
#define E_COARSE  262144

#define NODE_OUT_F   (N_COARSE * H)            // 16,777,216
#define EDGE_OUT_F   (E_COARSE * H)            // 67,108,864
#define ATTR_OUT_F   (NODE_OUT_F + EDGE_OUT_F) // 83,886,080
#define IDX_OUT_F    (2 * E_COARSE)            // 524,288

// ----- scratch (device globals; no allocation) ------------------------------
__device__ __align__(16) __half g_WT[3 * H * H];   // transposed fp16 weights
__device__ int g_ncnt[N_COARSE];
__device__ int g_ecnt[E_COARSE];
__device__ int g_noff[N_COARSE], g_ncur[N_COARSE];
__device__ int g_eoff[E_COARSE], g_ecur[E_COARSE];
__device__ int g_nperm[N_FINE];
__device__ int g_eperm[E_FINE];
__device__ int g_blk[256];
__device__ __align__(16) float g_fnp[(size_t)N_FINE * H];   // 256 MB staging

// ------------------------- small helpers -----------------------------------

__device__ __forceinline__ void mma16816_f16(float c[4], const unsigned a[4],
                                             unsigned b0, unsigned b1) {
    asm volatile(
        "mma.sync.aligned.m16n8k16.row.col.f32.f16.f16.f32 "
        "{%0,%1,%2,%3}, {%4,%5,%6,%7}, {%8,%9}, {%0,%1,%2,%3};\n"
        : "+f"(c[0]), "+f"(c[1]), "+f"(c[2]), "+f"(c[3])
        : "r"(a[0]), "r"(a[1]), "r"(a[2]), "r"(a[3]), "r"(b0), "r"(b1));
}

// split fp32 pair into fp16 hi + fp16 residual (packed b32 regs for MMA)
__device__ __forceinline__ void split2h(float a, float b, unsigned &hi, unsigned &lo) {
    __half2 h2 = __floats2half2_rn(a, b);
    float2 hf = __half22float2(h2);
    __half2 l2 = __floats2half2_rn(a - hf.x, b - hf.y);
    hi = *reinterpret_cast<unsigned*>(&h2);
    lo = *reinterpret_cast<unsigned*>(&l2);
}

__device__ __forceinline__ float elu(float v) {
    return v > 0.0f ? v : expm1f(v);
}

// ------------------------- prep: transpose weights to fp16 ------------------
// g_WT[l][n*256 + k] = fp16( W_l[k][n] ) ; layer0 uses W1 rows 0..255.

__global__ void prep_weights_kernel(const float* __restrict__ W1,
                                    const float* __restrict__ W2,
                                    const float* __restrict__ W3) {
    int t = blockIdx.x * 256 + threadIdx.x;       // < 3*65536
    int l = t >> 16;
    int r = t & 65535;
    int n = r >> 8, k = r & 255;
    const float* W = (l == 0) ? W1 : (l == 1 ? W2 : W3);
    g_WT[t] = __float2half_rn(W[k * H + n]);
}

// ------------------------- counts ------------------------------------------

__global__ void zero_counts_kernel() {
    int i = blockIdx.x * 256 + threadIdx.x;       // < E_COARSE
    g_ecnt[i] = 0;
    if (i < N_COARSE) g_ncnt[i] = 0;
}

__global__ void count_kernel(const int* __restrict__ f2c,
                             const int* __restrict__ f2ce) {
    int i = blockIdx.x * 256 + threadIdx.x;       // < E_FINE
    atomicAdd(&g_ecnt[f2ce[i]], 1);
    if (i < N_FINE) atomicAdd(&g_ncnt[f2c[i]], 1);
}

// ------------------------- CSR build: scan + bucket fill --------------------

__global__ void scan_block_kernel(int which) {
    __shared__ int s[1024];
    const int* cnt = which ? g_ncnt : g_ecnt;
    int*       out = which ? g_noff : g_eoff;
    int t   = threadIdx.x;
    int gid = blockIdx.x * 1024 + t;
    int v = cnt[gid];
    s[t] = v;
    __syncthreads();
#pragma unroll
    for (int off = 1; off < 1024; off <<= 1) {
        int xv = (t >= off) ? s[t - off] : 0;
        __syncthreads();
        s[t] += xv;
        __syncthreads();
    }
    out[gid] = s[t] - v;
    if (t == 1023) g_blk[blockIdx.x] = s[t];
}

__global__ void scan_tops_kernel(int nb) {
    __shared__ int s[256];
    int t = threadIdx.x;
    int v = (t < nb) ? g_blk[t] : 0;
    s[t] = v;
    __syncthreads();
#pragma unroll
    for (int off = 1; off < 256; off <<= 1) {
        int xv = (t >= off) ? s[t - off] : 0;
        __syncthreads();
        s[t] += xv;
        __syncthreads();
    }
    if (t < nb) g_blk[t] = s[t] - v;
}

__global__ void scan_add_kernel(int which) {
    int gid = blockIdx.x * 256 + threadIdx.x;
    int* out = which ? g_noff : g_eoff;
    int* cur = which ? g_ncur : g_ecur;
    int v = out[gid] + g_blk[gid >> 10];
    out[gid] = v;
    cur[gid] = v;
}

__global__ void fill_perm_kernel(const int* __restrict__ f2c,
                                 const int* __restrict__ f2ce) {
    int i = blockIdx.x * 256 + threadIdx.x;       // < E_FINE
    int ce = f2ce[i];
    int p = atomicAdd(&g_ecur[ce], 1);
    g_eperm[p] = i;
    if (i < N_FINE) {
        int cn = f2c[i];
        int q = atomicAdd(&g_ncur[cn], 1);
        g_nperm[q] = i;
    }
}

// ------------------------- gather (sum + mean, single write) ----------------

__global__ void edge_gather_kernel(const float* __restrict__ ea,
                                   float* __restrict__ out_edge) {
    int t  = blockIdx.x * 256 + threadIdx.x;      // < E_COARSE*64
    int ce = t >> 6;
    int c  = (t & 63) * 4;
    int start = g_eoff[ce];
    int deg   = g_ecnt[ce];
    float4 s = make_float4(0.f, 0.f, 0.f, 0.f);
    for (int j = 0; j < deg; ++j) {
        int row = g_eperm[start + j];
        float4 v = *reinterpret_cast<const float4*>(ea + (size_t)row * H + c);
        s.x += v.x; s.y += v.y; s.z += v.z; s.w += v.w;
    }
    float inv = 1.0f / fmaxf((float)deg, 1.0f);
    s.x *= inv; s.y *= inv; s.z *= inv; s.w *= inv;
    *reinterpret_cast<float4*>(out_edge + (size_t)ce * H + c) = s;
}

__global__ void node_gather_kernel(float* __restrict__ out_node) {
    int t  = blockIdx.x * 256 + threadIdx.x;      // < N_COARSE*64
    int cn = t >> 6;
    int c  = (t & 63) * 4;
    int start = g_noff[cn];
    int deg   = g_ncnt[cn];
    float4 s = make_float4(0.f, 0.f, 0.f, 0.f);
    for (int j = 0; j < deg; ++j) {
        int row = g_nperm[start + j];
        float4 v = *reinterpret_cast<const float4*>(g_fnp + (size_t)row * H + c);
        s.x += v.x; s.y += v.y; s.z += v.z; s.w += v.w;
    }
    float inv = 1.0f / fmaxf((float)deg, 1.0f);
    s.x *= inv; s.y *= inv; s.z *= inv; s.w *= inv;
    *reinterpret_cast<float4*>(out_node + (size_t)cn * H + c) = s;
}

// ------------------------- fused node MLP (writes g_fnp) -------------------
// Block: 512 threads (16 warps as 4m x 4n), tile M=128, N=256, K streamed.
// SMEM: As fp32 [128][260] (x, then h1, then h2), B double-buffered fp16
// transposed chunks [256 n][40 pitch] (k chunk = 32).

#define APITCH 260
#define BPITCH 40
#define AS_BYTES   (128 * APITCH * 4)                 // 133,120
#define BS_ELEMS_1 (H * BPITCH)                       // 10,240 halves per buffer
#define BS_BYTES   (2 * BS_ELEMS_1 * 2)               // 40,960
#define DS_OFF     (AS_BYTES + BS_BYTES)              // 174,080
#define SMEM_BYTES (DS_OFF + 512)                     // 174,592

__device__ __forceinline__ void loadB(__half* Bs,
                                      const __half* __restrict__ Wh,
                                      int t, int buf, int k0) {
    int r = t >> 1, hh = t & 1;                   // row, 16-elem half
    const __half* src = Wh + r * H + k0 + hh * 16;
    __half* dst = Bs + buf * BS_ELEMS_1 + r * BPITCH + hh * 16;
    uint4 v0 = *reinterpret_cast<const uint4*>(src);
    uint4 v1 = *reinterpret_cast<const uint4*>(src + 8);
    *reinterpret_cast<uint4*>(dst)     = v0;
    *reinterpret_cast<uint4*>(dst + 8) = v1;
}

__global__ void __launch_bounds__(512, 1)
node_fused_kernel(const float* __restrict__ x,
                  const float* __restrict__ dist,
                  const float* __restrict__ W1,   // for distance row (row 256)
                  const float* __restrict__ b1,
                  const float* __restrict__ b2,
                  const float* __restrict__ b3) {
    extern __shared__ char sm[];
    float*  As = reinterpret_cast<float*>(sm);
    __half* Bs = reinterpret_cast<__half*>(sm + AS_BYTES);
    float*  ds = reinterpret_cast<float*>(sm + DS_OFF);

    const int t = threadIdx.x;
    const int lane = t & 31, warp = t >> 5;
    const int g = lane >> 2, tg = lane & 3;
    const int wy = warp >> 2, wx = warp & 3;
    const int m0 = blockIdx.x * 128;
    const float* w1last = W1 + H * H;

    for (int i = t; i < 128 * 64; i += 512) {
        int r = i >> 6, c = (i & 63) << 2;
        float4 v = *reinterpret_cast<const float4*>(x + (size_t)(m0 + r) * H + c);
        float* d = As + r * APITCH + c;
        d[0] = v.x; d[1] = v.y; d[2] = v.z; d[3] = v.w;
    }
    if (t < 128) ds[t] = dist[m0 + t];

    float acc[2][8][4];

#pragma unroll 1
    for (int layer = 0; layer < 3; ++layer) {
#pragma unroll
        for (int a = 0; a < 2; ++a)
#pragma unroll
            for (int b = 0; b < 8; ++b)
#pragma unroll
                for (int q = 0; q < 4; ++q) acc[a][b][q] = 0.0f;

        const __half* Wh = g_WT + layer * (H * H);

        loadB(Bs, Wh, t, 0, 0);
        __syncthreads();

#pragma unroll 1
        for (int c = 0; c < 8; ++c) {
            if (c < 7) loadB(Bs, Wh, t, (c + 1) & 1, (c + 1) * 32);

            const __half* Bh = Bs + (c & 1) * BS_ELEMS_1;
#pragma unroll
            for (int ks = 0; ks < 32; ks += 16) {
                unsigned ah[2][4], al[2][4];
                const int kk = c * 32 + ks + 2 * tg;
#pragma unroll
                for (int mt = 0; mt < 2; ++mt) {
                    const float* ap = As + (wy * 32 + mt * 16 + g) * APITCH + kk;
                    float2 p0 = *reinterpret_cast<const float2*>(ap);
                    float2 p1 = *reinterpret_cast<const float2*>(ap + 8 * APITCH);
                    float2 p2 = *reinterpret_cast<const float2*>(ap + 8);
                    float2 p3 = *reinterpret_cast<const float2*>(ap + 8 * APITCH + 8);
                    split2h(p0.x, p0.y, ah[mt][0], al[mt][0]);
                    split2h(p1.x, p1.y, ah[mt][1], al[mt][1]);
                    split2h(p2.x, p2.y, ah[mt][2], al[mt][2]);
                    split2h(p3.x, p3.y, ah[mt][3], al[mt][3]);
                }
#pragma unroll
                for (int nt = 0; nt < 8; ++nt) {
                    const __half* pb = Bh + (wx * 64 + nt * 8 + g) * BPITCH + ks + 2 * tg;
                    unsigned b0 = *reinterpret_cast<const unsigned*>(pb);
                    unsigned b1 = *reinterpret_cast<const unsigned*>(pb + 8);
#pragma unroll
                    for (int mt = 0; mt < 2; ++mt) {
                        mma16816_f16(acc[mt][nt], ah[mt], b0, b1);  // hi * B
                        mma16816_f16(acc[mt][nt], al[mt], b0, b1);  // lo * B
                    }
                }
            }
            __syncthreads();
        }

        // ---- epilogue ----
        const float* bias = (layer == 0) ? b1 : (layer == 1 ? b2 : b3);
#pragma unroll
        for (int mt = 0; mt < 2; ++mt) {
            const int r = wy * 32 + mt * 16 + g;
#pragma unroll
            for (int nt = 0; nt < 8; ++nt) {
                const int n = wx * 64 + nt * 8 + 2 * tg;
                float2 bv = *reinterpret_cast<const float2*>(bias + n);
                float v0 = acc[mt][nt][0] + bv.x;
                float v1 = acc[mt][nt][1] + bv.y;
                float v2 = acc[mt][nt][2] + bv.x;
                float v3 = acc[mt][nt][3] + bv.y;
                if (layer == 0) {   // distance rank-1 term of [x|d] @ W1
                    float2 wd = *reinterpret_cast<const float2*>(w1last + n);
                    v0 += ds[r] * wd.x;     v1 += ds[r] * wd.y;
                    v2 += ds[r + 8] * wd.x; v3 += ds[r + 8] * wd.y;
                }
                if (layer < 2) {
                    v0 = elu(v0); v1 = elu(v1); v2 = elu(v2); v3 = elu(v3);
                    *reinterpret_cast<float2*>(As + r * APITCH + n)       = make_float2(v0, v1);
                    *reinterpret_cast<float2*>(As + (r + 8) * APITCH + n) = make_float2(v2, v3);
                } else {
                    float2 x0 = *reinterpret_cast<const float2*>(x + (size_t)(m0 + r) * H + n);
                    float2 x1 = *reinterpret_cast<const float2*>(x + (size_t)(m0 + r + 8) * H + n);
                    v0 += x0.x; v1 += x0.y; v2 += x1.x; v3 += x1.y;
                    *reinterpret_cast<float2*>(g_fnp + (size_t)(m0 + r) * H + n)     = make_float2(v0, v1);
                    *reinterpret_cast<float2*>(g_fnp + (size_t)(m0 + r + 8) * H + n) = make_float2(v2, v3);
                }
            }
        }
        // next layer's post-prefetch __syncthreads orders As writes vs reads
    }
}

// ------------------------- index cast ---------------------------------------

__global__ void idx_cast_kernel(const int* __restrict__ cei,
                                float* __restrict__ out_idx) {
    int i = blockIdx.x * 256 + threadIdx.x;       // < IDX_OUT_F/4
    int4 e = *reinterpret_cast<const int4*>(cei + (size_t)i * 4);
    float4 f = make_float4((float)e.x, (float)e.y, (float)e.z, (float)e.w);
    *reinterpret_cast<float4*>(out_idx + (size_t)i * 4) = f;
}

// ------------------------- launch ------------------------------------------

extern "C" void kernel_launch(void* const* d_in, const int* in_sizes, int n_in,
                              void* d_out, int out_size) {
    const float* x    = (const float*)d_in[0];
    const float* ea   = (const float*)d_in[1];
    const float* dist = (const float*)d_in[2];
    const int*   f2c  = (const int*)d_in[3];
    const int*   f2ce = (const int*)d_in[4];
    const int*   cei  = (const int*)d_in[5];
    const float* W1   = (const float*)d_in[6];
    const float* b1   = (const float*)d_in[7];
    const float* W2   = (const float*)d_in[8];
    const float* b2   = (const float*)d_in[9];
    const float* W3   = (const float*)d_in[10];
    const float* b3   = (const float*)d_in[11];

    float* out      = (float*)d_out;
    float* out_node = out;
    float* out_edge = out + NODE_OUT_F;
    float* out_idx  = out + ATTR_OUT_F;

    cudaFuncSetAttribute(node_fused_kernel,
                         cudaFuncAttributeMaxDynamicSharedMemorySize, SMEM_BYTES);

    prep_weights_kernel<<<(3 * H * H) / 256, 256>>>(W1, W2, W3);
    zero_counts_kernel<<<E_COARSE / 256, 256>>>();
    count_kernel<<<E_FINE / 256, 256>>>(f2c, f2ce);

    // edge CSR
    scan_block_kernel<<<E_COARSE / 1024, 1024>>>(0);
    scan_tops_kernel<<<1, 256>>>(E_COARSE / 1024);
    scan_add_kernel<<<E_COARSE / 256, 256>>>(0);
    // node CSR
    scan_block_kernel<<<N_COARSE / 1024, 1024>>>(1);
    scan_tops_kernel<<<1, 256>>>(N_COARSE / 1024);
    scan_add_kernel<<<N_COARSE / 256, 256>>>(1);

    fill_perm_kernel<<<E_FINE / 256, 256>>>(f2c, f2ce);

    edge_gather_kernel<<<(E_COARSE * 64) / 256, 256>>>(ea, out_edge);

    node_fused_kernel<<<N_FINE / 128, 512, SMEM_BYTES>>>(
        x, dist, W1, b1, b2, b3);
    node_gather_kernel<<<(N_COARSE * 64) / 256, 256>>>(out_node);

    idx_cast_kernel<<<(IDX_OUT_F / 4) / 256, 256>>>(cei, out_idx);
}

// round 12
// speedup vs baseline: 1.7005x; 1.0092x over previous
#include <cuda_runtime.h>
#include <cuda_bf16.h>
#include <cuda_fp16.h>
#include <cstdint>

// ---------------------------------------------------------------------------
// MultiscaleMessagePassing on GB300 (sm_103 target — no tcgen05 available)
// R10: R6 proven structure; node MLP numeric scheme switched from bf16
//      3-term splitting to fp16 2-term splitting (A split hi/lo, B single
//      fp16). 48 -> 32 HMMA per warp-kstep.
//
// Outputs (concatenated float32 in d_out):
//   [0 .. 16,777,216)                 coarse_node_attrs  [65536, 256]
//   [16,777,216 .. 83,886,080)        coarse_edge_attrs  [262144, 256]
//   [83,886,080 .. 84,410,368)        coarse_edge_index  [2, 262144] (cast)
// ---------------------------------------------------------------------------

#define H         256
#define N_FINE    262144
#define E_FINE    524288
#define N_COARSE  65536
#define E_COARSE  262144

#define NODE_OUT_F   (N_COARSE * H)            // 16,777,216
#define EDGE_OUT_F   (E_COARSE * H)            // 67,108,864
#define ATTR_OUT_F   (NODE_OUT_F + EDGE_OUT_F) // 83,886,080
#define IDX_OUT_F    (2 * E_COARSE)            // 524,288

// ----- scratch (device globals; no allocation) ------------------------------
__device__ __align__(16) __half g_WT[3 * H * H];   // transposed fp16 weights
__device__ int g_ncnt[N_COARSE];
__device__ int g_ecnt[E_COARSE];
__device__ int g_noff[N_COARSE], g_ncur[N_COARSE];
__device__ int g_eoff[E_COARSE], g_ecur[E_COARSE];
__device__ int g_nperm[N_FINE];
__device__ int g_eperm[E_FINE];
__device__ int g_blk[256];
__device__ __align__(16) float g_fnp[(size_t)N_FINE * H];   // 256 MB staging

// ------------------------- small helpers -----------------------------------

__device__ __forceinline__ void mma16816_f16(float c[4], const unsigned a[4],
                                             unsigned b0, unsigned b1) {
    asm volatile(
        "mma.sync.aligned.m16n8k16.row.col.f32.f16.f16.f32 "
        "{%0,%1,%2,%3}, {%4,%5,%6,%7}, {%8,%9}, {%0,%1,%2,%3};\n"
        : "+f"(c[0]), "+f"(c[1]), "+f"(c[2]), "+f"(c[3])
        : "r"(a[0]), "r"(a[1]), "r"(a[2]), "r"(a[3]), "r"(b0), "r"(b1));
}

// split fp32 pair into fp16 hi + fp16 residual (packed b32 regs for MMA)
__device__ __forceinline__ void split2h(float a, float b, unsigned &hi, unsigned &lo) {
    __half2 h2 = __floats2half2_rn(a, b);
    float2 hf = __half22float2(h2);
    __half2 l2 = __floats2half2_rn(a - hf.x, b - hf.y);
    hi = *reinterpret_cast<unsigned*>(&h2);
    lo = *reinterpret_cast<unsigned*>(&l2);
}

__device__ __forceinline__ float elu(float v) {
    return v > 0.0f ? v : expm1f(v);
}

// ------------------------- prep: transpose weights to fp16 ------------------
// g_WT[l][n*256 + k] = fp16( W_l[k][n] ) ; layer0 uses W1 rows 0..255.

__global__ void prep_weights_kernel(const float* __restrict__ W1,
                                    const float* __restrict__ W2,
                                    const float* __restrict__ W3) {
    int t = blockIdx.x * 256 + threadIdx.x;       // < 3*65536
    int l = t >> 16;
    int r = t & 65535;
    int n = r >> 8, k = r & 255;
    const float* W = (l == 0) ? W1 : (l == 1 ? W2 : W3);
    g_WT[t] = __float2half_rn(W[k * H + n]);
}

// ------------------------- counts ------------------------------------------

__global__ void zero_counts_kernel() {
    int i = blockIdx.x * 256 + threadIdx.x;       // < E_COARSE
    g_ecnt[i] = 0;
    if (i < N_COARSE) g_ncnt[i] = 0;
}

__global__ void count_kernel(const int* __restrict__ f2c,
                             const int* __restrict__ f2ce) {
    int i = blockIdx.x * 256 + threadIdx.x;       // < E_FINE
    atomicAdd(&g_ecnt[f2ce[i]], 1);
    if (i < N_FINE) atomicAdd(&g_ncnt[f2c[i]], 1);
}

// ------------------------- CSR build: scan + bucket fill --------------------

__global__ void scan_block_kernel(int which) {
    __shared__ int s[1024];
    const int* cnt = which ? g_ncnt : g_ecnt;
    int*       out = which ? g_noff : g_eoff;
    int t   = threadIdx.x;
    int gid = blockIdx.x * 1024 + t;
    int v = cnt[gid];
    s[t] = v;
    __syncthreads();
#pragma unroll
    for (int off = 1; off < 1024; off <<= 1) {
        int xv = (t >= off) ? s[t - off] : 0;
        __syncthreads();
        s[t] += xv;
        __syncthreads();
    }
    out[gid] = s[t] - v;
    if (t == 1023) g_blk[blockIdx.x] = s[t];
}

__global__ void scan_tops_kernel(int nb) {
    __shared__ int s[256];
    int t = threadIdx.x;
    int v = (t < nb) ? g_blk[t] : 0;
    s[t] = v;
    __syncthreads();
#pragma unroll
    for (int off = 1; off < 256; off <<= 1) {
        int xv = (t >= off) ? s[t - off] : 0;
        __syncthreads();
        s[t] += xv;
        __syncthreads();
    }
    if (t < nb) g_blk[t] = s[t] - v;
}

__global__ void scan_add_kernel(int which) {
    int gid = blockIdx.x * 256 + threadIdx.x;
    int* out = which ? g_noff : g_eoff;
    int* cur = which ? g_ncur : g_ecur;
    int v = out[gid] + g_blk[gid >> 10];
    out[gid] = v;
    cur[gid] = v;
}

__global__ void fill_perm_kernel(const int* __restrict__ f2c,
                                 const int* __restrict__ f2ce) {
    int i = blockIdx.x * 256 + threadIdx.x;       // < E_FINE
    int ce = f2ce[i];
    int p = atomicAdd(&g_ecur[ce], 1);
    g_eperm[p] = i;
    if (i < N_FINE) {
        int cn = f2c[i];
        int q = atomicAdd(&g_ncur[cn], 1);
        g_nperm[q] = i;
    }
}

// ------------------------- gather (sum + mean, single write) ----------------

__global__ void edge_gather_kernel(const float* __restrict__ ea,
                                   float* __restrict__ out_edge) {
    int t  = blockIdx.x * 256 + threadIdx.x;      // < E_COARSE*64
    int ce = t >> 6;
    int c  = (t & 63) * 4;
    int start = g_eoff[ce];
    int deg   = g_ecnt[ce];
    float4 s = make_float4(0.f, 0.f, 0.f, 0.f);
    for (int j = 0; j < deg; ++j) {
        int row = g_eperm[start + j];
        float4 v = *reinterpret_cast<const float4*>(ea + (size_t)row * H + c);
        s.x += v.x; s.y += v.y; s.z += v.z; s.w += v.w;
    }
    float inv = 1.0f / fmaxf((float)deg, 1.0f);
    s.x *= inv; s.y *= inv; s.z *= inv; s.w *= inv;
    *reinterpret_cast<float4*>(out_edge + (size_t)ce * H + c) = s;
}

__global__ void node_gather_kernel(float* __restrict__ out_node) {
    int t  = blockIdx.x * 256 + threadIdx.x;      // < N_COARSE*64
    int cn = t >> 6;
    int c  = (t & 63) * 4;
    int start = g_noff[cn];
    int deg   = g_ncnt[cn];
    float4 s = make_float4(0.f, 0.f, 0.f, 0.f);
    for (int j = 0; j < deg; ++j) {
        int row = g_nperm[start + j];
        float4 v = *reinterpret_cast<const float4*>(g_fnp + (size_t)row * H + c);
        s.x += v.x; s.y += v.y; s.z += v.z; s.w += v.w;
    }
    float inv = 1.0f / fmaxf((float)deg, 1.0f);
    s.x *= inv; s.y *= inv; s.z *= inv; s.w *= inv;
    *reinterpret_cast<float4*>(out_node + (size_t)cn * H + c) = s;
}

// ------------------------- fused node MLP (writes g_fnp) -------------------
// Block: 512 threads (16 warps as 4m x 4n), tile M=128, N=256, K streamed.
// SMEM: As fp32 [128][260] (x, then h1, then h2), B double-buffered fp16
// transposed chunks [256 n][40 pitch] (k chunk = 32).

#define APITCH 260
#define BPITCH 40
#define AS_BYTES   (128 * APITCH * 4)                 // 133,120
#define BS_ELEMS_1 (H * BPITCH)                       // 10,240 halves per buffer
#define BS_BYTES   (2 * BS_ELEMS_1 * 2)               // 40,960
#define DS_OFF     (AS_BYTES + BS_BYTES)              // 174,080
#define SMEM_BYTES (DS_OFF + 512)                     // 174,592

__device__ __forceinline__ void loadB(__half* Bs,
                                      const __half* __restrict__ Wh,
                                      int t, int buf, int k0) {
    int r = t >> 1, hh = t & 1;                   // row, 16-elem half
    const __half* src = Wh + r * H + k0 + hh * 16;
    __half* dst = Bs + buf * BS_ELEMS_1 + r * BPITCH + hh * 16;
    uint4 v0 = *reinterpret_cast<const uint4*>(src);
    uint4 v1 = *reinterpret_cast<const uint4*>(src + 8);
    *reinterpret_cast<uint4*>(dst)     = v0;
    *reinterpret_cast<uint4*>(dst + 8) = v1;
}

__global__ void __launch_bounds__(512, 1)
node_fused_kernel(const float* __restrict__ x,
                  const float* __restrict__ dist,
                  const float* __restrict__ W1,   // for distance row (row 256)
                  const float* __restrict__ b1,
                  const float* __restrict__ b2,
                  const float* __restrict__ b3) {
    extern __shared__ char sm[];
    float*  As = reinterpret_cast<float*>(sm);
    __half* Bs = reinterpret_cast<__half*>(sm + AS_BYTES);
    float*  ds = reinterpret_cast<float*>(sm + DS_OFF);

    const int t = threadIdx.x;
    const int lane = t & 31, warp = t >> 5;
    const int g = lane >> 2, tg = lane & 3;
    const int wy = warp >> 2, wx = warp & 3;
    const int m0 = blockIdx.x * 128;
    const float* w1last = W1 + H * H;

    for (int i = t; i < 128 * 64; i += 512) {
        int r = i >> 6, c = (i & 63) << 2;
        float4 v = *reinterpret_cast<const float4*>(x + (size_t)(m0 + r) * H + c);
        float* d = As + r * APITCH + c;
        d[0] = v.x; d[1] = v.y; d[2] = v.z; d[3] = v.w;
    }
    if (t < 128) ds[t] = dist[m0 + t];

    float acc[2][8][4];

#pragma unroll 1
    for (int layer = 0; layer < 3; ++layer) {
#pragma unroll
        for (int a = 0; a < 2; ++a)
#pragma unroll
            for (int b = 0; b < 8; ++b)
#pragma unroll
                for (int q = 0; q < 4; ++q) acc[a][b][q] = 0.0f;

        const __half* Wh = g_WT + layer * (H * H);

        loadB(Bs, Wh, t, 0, 0);
        __syncthreads();

#pragma unroll 1
        for (int c = 0; c < 8; ++c) {
            if (c < 7) loadB(Bs, Wh, t, (c + 1) & 1, (c + 1) * 32);

            const __half* Bh = Bs + (c & 1) * BS_ELEMS_1;
#pragma unroll
            for (int ks = 0; ks < 32; ks += 16) {
                unsigned ah[2][4], al[2][4];
                const int kk = c * 32 + ks + 2 * tg;
#pragma unroll
                for (int mt = 0; mt < 2; ++mt) {
                    const float* ap = As + (wy * 32 + mt * 16 + g) * APITCH + kk;
                    float2 p0 = *reinterpret_cast<const float2*>(ap);
                    float2 p1 = *reinterpret_cast<const float2*>(ap + 8 * APITCH);
                    float2 p2 = *reinterpret_cast<const float2*>(ap + 8);
                    float2 p3 = *reinterpret_cast<const float2*>(ap + 8 * APITCH + 8);
                    split2h(p0.x, p0.y, ah[mt][0], al[mt][0]);
                    split2h(p1.x, p1.y, ah[mt][1], al[mt][1]);
                    split2h(p2.x, p2.y, ah[mt][2], al[mt][2]);
                    split2h(p3.x, p3.y, ah[mt][3], al[mt][3]);
                }
#pragma unroll
                for (int nt = 0; nt < 8; ++nt) {
                    const __half* pb = Bh + (wx * 64 + nt * 8 + g) * BPITCH + ks + 2 * tg;
                    unsigned b0 = *reinterpret_cast<const unsigned*>(pb);
                    unsigned b1 = *reinterpret_cast<const unsigned*>(pb + 8);
#pragma unroll
                    for (int mt = 0; mt < 2; ++mt) {
                        mma16816_f16(acc[mt][nt], ah[mt], b0, b1);  // hi * B
                        mma16816_f16(acc[mt][nt], al[mt], b0, b1);  // lo * B
                    }
                }
            }
            __syncthreads();
        }

        // ---- epilogue ----
        const float* bias = (layer == 0) ? b1 : (layer == 1 ? b2 : b3);
#pragma unroll
        for (int mt = 0; mt < 2; ++mt) {
            const int r = wy * 32 + mt * 16 + g;
#pragma unroll
            for (int nt = 0; nt < 8; ++nt) {
                const int n = wx * 64 + nt * 8 + 2 * tg;
                float2 bv = *reinterpret_cast<const float2*>(bias + n);
                float v0 = acc[mt][nt][0] + bv.x;
                float v1 = acc[mt][nt][1] + bv.y;
                float v2 = acc[mt][nt][2] + bv.x;
                float v3 = acc[mt][nt][3] + bv.y;
                if (layer == 0) {   // distance rank-1 term of [x|d] @ W1
                    float2 wd = *reinterpret_cast<const float2*>(w1last + n);
                    v0 += ds[r] * wd.x;     v1 += ds[r] * wd.y;
                    v2 += ds[r + 8] * wd.x; v3 += ds[r + 8] * wd.y;
                }
                if (layer < 2) {
                    v0 = elu(v0); v1 = elu(v1); v2 = elu(v2); v3 = elu(v3);
                    *reinterpret_cast<float2*>(As + r * APITCH + n)       = make_float2(v0, v1);
                    *reinterpret_cast<float2*>(As + (r + 8) * APITCH + n) = make_float2(v2, v3);
                } else {
                    float2 x0 = *reinterpret_cast<const float2*>(x + (size_t)(m0 + r) * H + n);
                    float2 x1 = *reinterpret_cast<const float2*>(x + (size_t)(m0 + r + 8) * H + n);
                    v0 += x0.x; v1 += x0.y; v2 += x1.x; v3 += x1.y;
                    *reinterpret_cast<float2*>(g_fnp + (size_t)(m0 + r) * H + n)     = make_float2(v0, v1);
                    *reinterpret_cast<float2*>(g_fnp + (size_t)(m0 + r + 8) * H + n) = make_float2(v2, v3);
                }
            }
        }
        // next layer's post-prefetch __syncthreads orders As writes vs reads
    }
}

// ------------------------- index cast ---------------------------------------

__global__ void idx_cast_kernel(const int* __restrict__ cei,
                                float* __restrict__ out_idx) {
    int i = blockIdx.x * 256 + threadIdx.x;       // < IDX_OUT_F/4
    int4 e = *reinterpret_cast<const int4*>(cei + (size_t)i * 4);
    float4 f = make_float4((float)e.x, (float)e.y, (float)e.z, (float)e.w);
    *reinterpret_cast<float4*>(out_idx + (size_t)i * 4) = f;
}

// ------------------------- launch ------------------------------------------

extern "C" void kernel_launch(void* const* d_in, const int* in_sizes, int n_in,
                              void* d_out, int out_size) {
    const float* x    = (const float*)d_in[0];
    const float* ea   = (const float*)d_in[1];
    const float* dist = (const float*)d_in[2];
    const int*   f2c  = (const int*)d_in[3];
    const int*   f2ce = (const int*)d_in[4];
    const int*   cei  = (const int*)d_in[5];
    const float* W1   = (const float*)d_in[6];
    const float* b1   = (const float*)d_in[7];
    const float* W2   = (const float*)d_in[8];
    const float* b2   = (const float*)d_in[9];
    const float* W3   = (const float*)d_in[10];
    const float* b3   = (const float*)d_in[11];

    float* out      = (float*)d_out;
    float* out_node = out;
    float* out_edge = out + NODE_OUT_F;
    float* out_idx  = out + ATTR_OUT_F;

    cudaFuncSetAttribute(node_fused_kernel,
                         cudaFuncAttributeMaxDynamicSharedMemorySize, SMEM_BYTES);

    prep_weights_kernel<<<(3 * H * H) / 256, 256>>>(W1, W2, W3);
    zero_counts_kernel<<<E_COARSE / 256, 256>>>();
    count_kernel<<<E_FINE / 256, 256>>>(f2c, f2ce);

    // edge CSR
    scan_block_kernel<<<E_COARSE / 1024, 1024>>>(0);
    scan_tops_kernel<<<1, 256>>>(E_COARSE / 1024);
    scan_add_kernel<<<E_COARSE / 256, 256>>>(0);
    // node CSR
    scan_block_kernel<<<N_COARSE / 1024, 1024>>>(1);
    scan_tops_kernel<<<1, 256>>>(N_COARSE / 1024);
    scan_add_kernel<<<N_COARSE / 256, 256>>>(1);

    fill_perm_kernel<<<E_FINE / 256, 256>>>(f2c, f2ce);

    edge_gather_kernel<<<(E_COARSE * 64) / 256, 256>>>(ea, out_edge);

    node_fused_kernel<<<N_FINE / 128, 512, SMEM_BYTES>>>(
        x, dist, W1, b1, b2, b3);
    node_gather_kernel<<<(N_COARSE * 64) / 256, 256>>>(out_node);

    idx_cast_kernel<<<(IDX_OUT_F / 4) / 256, 256>>>(cei, out_idx);
}